// round 1
// baseline (speedup 1.0000x reference)
#include <cuda_runtime.h>
#include <cstdint>
#include <cstddef>

// Problem constants
#define NR 8192
#define DD 512

// ---------------------------------------------------------------------------
// Device scratch (static allocation — no cudaMalloc allowed)
// ---------------------------------------------------------------------------
__device__ float  g_logits[(size_t)NR * NR];   // 268 MB logits scratch
__device__ float  g_c2[NR];
__device__ float  g_t2[NR];
// accumulators:
// [0] = S_exp_off   (sum of exp(logit) over off-diagonal) = sum 1/(1+d2)
// [1] = sum_logit_diag
// [2] = sum_sig_diag
// [3] = cnt_diag (>0 count, as double)
// [4] = sum_logit_all
// [5] = sum_sig_all
// [6] = cnt_all (as double)
// [7] = log_baseline
__device__ double g_acc[16];

// ---------------------------------------------------------------------------
// 0) zero accumulators (must be reset every kernel_launch call)
// ---------------------------------------------------------------------------
__global__ void k_init() {
    if (threadIdx.x < 16) g_acc[threadIdx.x] = 0.0;
}

// ---------------------------------------------------------------------------
// 1) squared row norms of C and T.  16384 blocks, 128 threads, float4 loads.
// ---------------------------------------------------------------------------
__global__ void k_sqnorm(const float* __restrict__ C, const float* __restrict__ T) {
    int row = blockIdx.x;                     // 0..16383
    const float* src = (row < NR) ? (C + (size_t)row * DD)
                                  : (T + (size_t)(row - NR) * DD);
    float4 v = ((const float4*)src)[threadIdx.x];   // 128 threads * 4 = 512
    float s = v.x * v.x + v.y * v.y + v.z * v.z + v.w * v.w;
    #pragma unroll
    for (int o = 16; o > 0; o >>= 1) s += __shfl_down_sync(0xffffffffu, s, o);
    __shared__ float ws[4];
    if ((threadIdx.x & 31) == 0) ws[threadIdx.x >> 5] = s;
    __syncthreads();
    if (threadIdx.x == 0) {
        float t = ws[0] + ws[1] + ws[2] + ws[3];
        if (row < NR) g_c2[row] = t;
        else          g_t2[row - NR] = t;
    }
}

// ---------------------------------------------------------------------------
// 2) fused GEMM (C @ T^T) + logits + scratch store + Sum(exp(logit)) off-diag
//    128x128 block tile, BK=16, 256 threads, 8x8 per thread,
//    double-buffered shared memory.
// ---------------------------------------------------------------------------
__global__ __launch_bounds__(256, 2)
void k_gemm(const float* __restrict__ A, const float* __restrict__ B) {
    __shared__ float As[2][16][128];
    __shared__ float Bs[2][16][128];

    const int tid  = threadIdx.x;
    const int brow = blockIdx.y * 128;
    const int bcol = blockIdx.x * 128;
    const int ty   = tid >> 4;          // 0..15
    const int tx   = tid & 15;          // 0..15

    float acc[8][8];
    #pragma unroll
    for (int i = 0; i < 8; i++)
        #pragma unroll
        for (int j = 0; j < 8; j++) acc[i][j] = 0.0f;

    // loader mapping: 512 float4 per 128x16 tile; 2 per thread
    const int r0 = tid >> 2;            // 0..63
    const int q0 = tid & 3;             // 0..3
    const float4* A4 = (const float4*)A;
    const float4* B4 = (const float4*)B;

    float4 ra0, ra1, rb0, rb1;

    auto ldg = [&](int kt) {
        size_t kb = (size_t)kt * 4 + q0;
        ra0 = A4[(size_t)(brow + r0)      * (DD / 4) + kb];
        ra1 = A4[(size_t)(brow + r0 + 64) * (DD / 4) + kb];
        rb0 = B4[(size_t)(bcol + r0)      * (DD / 4) + kb];
        rb1 = B4[(size_t)(bcol + r0 + 64) * (DD / 4) + kb];
    };
    auto sts = [&](int buf) {
        As[buf][q0 * 4 + 0][r0] = ra0.x;  As[buf][q0 * 4 + 1][r0] = ra0.y;
        As[buf][q0 * 4 + 2][r0] = ra0.z;  As[buf][q0 * 4 + 3][r0] = ra0.w;
        As[buf][q0 * 4 + 0][r0 + 64] = ra1.x;  As[buf][q0 * 4 + 1][r0 + 64] = ra1.y;
        As[buf][q0 * 4 + 2][r0 + 64] = ra1.z;  As[buf][q0 * 4 + 3][r0 + 64] = ra1.w;
        Bs[buf][q0 * 4 + 0][r0] = rb0.x;  Bs[buf][q0 * 4 + 1][r0] = rb0.y;
        Bs[buf][q0 * 4 + 2][r0] = rb0.z;  Bs[buf][q0 * 4 + 3][r0] = rb0.w;
        Bs[buf][q0 * 4 + 0][r0 + 64] = rb1.x;  Bs[buf][q0 * 4 + 1][r0 + 64] = rb1.y;
        Bs[buf][q0 * 4 + 2][r0 + 64] = rb1.z;  Bs[buf][q0 * 4 + 3][r0 + 64] = rb1.w;
    };

    ldg(0);
    sts(0);
    __syncthreads();

    const int NKT = DD / 16;            // 32
    for (int kt = 0; kt < NKT; ++kt) {
        const int cur = kt & 1;
        if (kt + 1 < NKT) ldg(kt + 1);

        #pragma unroll
        for (int k = 0; k < 16; ++k) {
            float a[8], b[8];
            #pragma unroll
            for (int i = 0; i < 8; i++) a[i] = As[cur][k][ty * 8 + i];
            #pragma unroll
            for (int j = 0; j < 8; j++) b[j] = Bs[cur][k][tx * 8 + j];
            #pragma unroll
            for (int i = 0; i < 8; i++)
                #pragma unroll
                for (int j = 0; j < 8; j++)
                    acc[i][j] = fmaf(a[i], b[j], acc[i][j]);
        }

        if (kt + 1 < NKT) sts((kt + 1) & 1);
        __syncthreads();
    }

    // ---- epilogue: logits, scratch store, local Sum(1/(1+d2)) off-diag ----
    const int row0 = brow + ty * 8;
    const int col0 = bcol + tx * 8;
    float c2r[8], t2r[8];
    #pragma unroll
    for (int i = 0; i < 8; i++) c2r[i] = g_c2[row0 + i];
    #pragma unroll
    for (int j = 0; j < 8; j++) t2r[j] = g_t2[col0 + j];

    float sexp = 0.0f;
    #pragma unroll
    for (int i = 0; i < 8; i++) {
        float out[8];
        #pragma unroll
        for (int j = 0; j < 8; j++) {
            float d2 = fmaxf(c2r[i] + t2r[j] - 2.0f * acc[i][j], 0.0f);
            out[j] = -log1pf(d2);
            // exp(logit) == 1/(1+d2) exactly
            if ((row0 + i) != (col0 + j)) sexp += 1.0f / (1.0f + d2);
        }
        float4* dst = (float4*)&g_logits[(size_t)(row0 + i) * NR + col0];
        dst[0] = make_float4(out[0], out[1], out[2], out[3]);
        dst[1] = make_float4(out[4], out[5], out[6], out[7]);
    }

    __shared__ double red[256];
    red[tid] = (double)sexp;
    __syncthreads();
    #pragma unroll
    for (int s = 128; s > 0; s >>= 1) {
        if (tid < s) red[tid] += red[tid + s];
        __syncthreads();
    }
    if (tid == 0) atomicAdd(&g_acc[0], red[0]);
}

// ---------------------------------------------------------------------------
// 3) compute log_baseline, then diagonal statistics. single block, 256 thr.
// ---------------------------------------------------------------------------
__global__ void k_mid() {
    const int tid = threadIdx.x;
    __shared__ double s_lb;
    if (tid == 0) {
        double lb = log(g_acc[0]) - log((double)NR * (double)(NR - 1));
        g_acc[7] = lb;
        s_lb = lb;
    }
    __syncthreads();
    const float lbf = (float)s_lb;

    float slog = 0.0f, ssig = 0.0f;
    int cnt = 0;
    for (int i = tid; i < NR; i += 256) {
        float x = g_logits[(size_t)i * (NR + 1)];
        float y = x - lbf;
        slog += x;
        ssig += 1.0f / (1.0f + expf(-y));
        cnt  += (y > 0.0f) ? 1 : 0;
    }
    __shared__ double r0[256], r1[256];
    __shared__ int    r2[256];
    r0[tid] = (double)slog; r1[tid] = (double)ssig; r2[tid] = cnt;
    __syncthreads();
    for (int s = 128; s > 0; s >>= 1) {
        if (tid < s) { r0[tid] += r0[tid + s]; r1[tid] += r1[tid + s]; r2[tid] += r2[tid + s]; }
        __syncthreads();
    }
    if (tid == 0) { g_acc[1] = r0[0]; g_acc[2] = r1[0]; g_acc[3] = (double)r2[0]; }
}

// ---------------------------------------------------------------------------
// 4) streaming stats over ALL 67.1M logits (diag subtracted at finalize).
// ---------------------------------------------------------------------------
__global__ __launch_bounds__(256)
void k_stream() {
    const float lbf = (float)g_acc[7];
    const int tid = threadIdx.x;

    float  slog = 0.0f, ssig = 0.0f;
    int    cnt = 0;
    const size_t total4 = ((size_t)NR * NR) / 4;
    const size_t stride = (size_t)gridDim.x * blockDim.x;
    const float4* L4 = (const float4*)g_logits;

    for (size_t i = (size_t)blockIdx.x * blockDim.x + tid; i < total4; i += stride) {
        float4 v = L4[i];
        float y0 = v.x - lbf, y1 = v.y - lbf, y2 = v.z - lbf, y3 = v.w - lbf;
        slog += (v.x + v.y) + (v.z + v.w);
        ssig += 1.0f / (1.0f + expf(-y0));
        ssig += 1.0f / (1.0f + expf(-y1));
        ssig += 1.0f / (1.0f + expf(-y2));
        ssig += 1.0f / (1.0f + expf(-y3));
        cnt += (y0 > 0.0f) + (y1 > 0.0f) + (y2 > 0.0f) + (y3 > 0.0f);
    }

    __shared__ double r0[256], r1[256];
    __shared__ int    r2[256];
    r0[tid] = (double)slog; r1[tid] = (double)ssig; r2[tid] = cnt;
    __syncthreads();
    for (int s = 128; s > 0; s >>= 1) {
        if (tid < s) { r0[tid] += r0[tid + s]; r1[tid] += r1[tid + s]; r2[tid] += r2[tid + s]; }
        __syncthreads();
    }
    if (tid == 0) {
        atomicAdd(&g_acc[4], r0[0]);
        atomicAdd(&g_acc[5], r1[0]);
        atomicAdd(&g_acc[6], (double)r2[0]);
    }
}

// ---------------------------------------------------------------------------
// 5) finalize: 12 scalar outputs
// ---------------------------------------------------------------------------
__global__ void k_final(float* __restrict__ out) {
    if (threadIdx.x != 0 || blockIdx.x != 0) return;
    const double Npos = (double)NR;
    const double Nneg = (double)NR * (double)(NR - 1);

    double LB        = g_acc[7];
    double sdl       = g_acc[1];          // sum logit diag
    double sds       = g_acc[2];          // sum sigmoid diag
    double cntd      = g_acc[3];
    double sal       = g_acc[4];          // sum logit all
    double sas       = g_acc[5];          // sum sigmoid all
    double cnta      = g_acc[6];

    double pos_mean  = sdl / Npos - LB;
    double neg_mean  = (sal - sdl) / Nneg - LB;
    double repulsion = exp(-LB) * g_acc[0] / Nneg;   // == 1 analytically
    double loss      = -pos_mean + repulsion;
    double sig_pos   = sds / Npos;
    double sig_neg   = (sas - sds) / Nneg;

    double TP = cntd / Npos;
    double FP = (cnta - cntd) / Nneg;
    double TN = 1.0 - FP;
    double FN = 1.0 - TP;
    double accuracy  = (TP + TN) * 0.5;
    double precision = TP / (TP + FP);
    double npv       = TN / (TN + FN);
    double apv       = (precision + npv) * 0.5;

    out[0]  = (float)loss;
    out[1]  = (float)pos_mean;
    out[2]  = (float)neg_mean;
    out[3]  = (float)sig_pos;
    out[4]  = (float)sig_neg;
    out[5]  = (float)LB;
    out[6]  = (float)accuracy;
    out[7]  = (float)precision;
    out[8]  = (float)npv;
    out[9]  = (float)apv;
    out[10] = (float)TP;
    out[11] = (float)TN;
}

// ---------------------------------------------------------------------------
// launch
// ---------------------------------------------------------------------------
extern "C" void kernel_launch(void* const* d_in, const int* in_sizes, int n_in,
                              void* d_out, int out_size) {
    const float* C = (const float*)d_in[0];   // context_embedding (8192,512)
    const float* T = (const float*)d_in[1];   // target_embedding  (8192,512)
    float* out = (float*)d_out;

    k_init<<<1, 32>>>();
    k_sqnorm<<<2 * NR, 128>>>(C, T);
    dim3 grid(NR / 128, NR / 128);
    k_gemm<<<grid, 256>>>(C, T);
    k_mid<<<1, 256>>>();
    k_stream<<<2048, 256>>>();
    k_final<<<1, 32>>>(out);
}

// round 3
// speedup vs baseline: 3.3359x; 3.3359x over previous
#include <cuda_runtime.h>
#include <cstdint>
#include <cstddef>

#define NR 8192
#define DD 512

// ---------------------------------------------------------------------------
// Device scratch (static — no cudaMalloc allowed)
// ---------------------------------------------------------------------------
__device__ float  g_logits[(size_t)NR * NR];   // 268 MB logits scratch
__device__ float  g_ca[(size_t)NR * DD];       // tf32-rounded context
__device__ float  g_tb[(size_t)NR * DD];       // tf32-rounded target
__device__ float  g_c2[NR];
__device__ float  g_t2[NR];
// [0]=S_exp_off [1]=sum_logit_diag [2]=sum_sig_diag [3]=cnt_diag
// [4]=sum_logit_all [5]=sum_sig_all [6]=cnt_all [7]=log_baseline
__device__ double g_acc[16];
__device__ double g_sexp_bucket[64];

// ---------------------------------------------------------------------------
// helpers
// ---------------------------------------------------------------------------
__device__ __forceinline__ uint32_t smem_u32(const void* p) {
    uint32_t a;
    asm("{ .reg .u64 t; cvta.to.shared.u64 t, %1; cvt.u32.u64 %0, t; }"
        : "=r"(a) : "l"(p));
    return a;
}

#define SWZ(off) ((off) ^ (((off) >> 3) & 0x70))

#define LDSM_X4(r0, r1, r2, r3, addr)                                   \
    asm volatile("ldmatrix.sync.aligned.m8n8.x4.shared.b16 "            \
                 "{%0,%1,%2,%3}, [%4];"                                 \
                 : "=r"(r0), "=r"(r1), "=r"(r2), "=r"(r3) : "r"(addr))

#define MMA_TF32(d, a0, a1, a2, a3, b0, b1)                             \
    asm volatile("mma.sync.aligned.m16n8k8.row.col.f32.tf32.tf32.f32 "  \
                 "{%0,%1,%2,%3}, {%4,%5,%6,%7}, {%8,%9}, {%0,%1,%2,%3};"\
                 : "+f"((d)[0]), "+f"((d)[1]), "+f"((d)[2]), "+f"((d)[3])\
                 : "r"(a0), "r"(a1), "r"(a2), "r"(a3), "r"(b0), "r"(b1))

__device__ __forceinline__ uint32_t to_tf32(float x) {
    uint32_t u;
    asm("cvt.rna.tf32.f32 %0, %1;" : "=r"(u) : "f"(x));
    return u;
}

// ---------------------------------------------------------------------------
// 0) zero accumulators
// ---------------------------------------------------------------------------
__global__ void k_init() {
    if (threadIdx.x < 16) g_acc[threadIdx.x] = 0.0;
    if (threadIdx.x < 64) g_sexp_bucket[threadIdx.x] = 0.0;
}

// ---------------------------------------------------------------------------
// 1) prep: squared row norms (exact fp32) + tf32-rounded copies
// ---------------------------------------------------------------------------
__global__ void k_prep(const float* __restrict__ C, const float* __restrict__ T) {
    int row = blockIdx.x;                       // 0..16383
    const bool isC = (row < NR);
    const float* src = isC ? (C + (size_t)row * DD)
                           : (T + (size_t)(row - NR) * DD);
    float* dst = isC ? (g_ca + (size_t)row * DD)
                     : (g_tb + (size_t)(row - NR) * DD);

    float4 v = ((const float4*)src)[threadIdx.x];
    float s = v.x * v.x + v.y * v.y + v.z * v.z + v.w * v.w;

    uint4 r;
    r.x = to_tf32(v.x); r.y = to_tf32(v.y);
    r.z = to_tf32(v.z); r.w = to_tf32(v.w);
    ((uint4*)dst)[threadIdx.x] = r;

    #pragma unroll
    for (int o = 16; o > 0; o >>= 1) s += __shfl_down_sync(0xffffffffu, s, o);
    __shared__ float ws[4];
    if ((threadIdx.x & 31) == 0) ws[threadIdx.x >> 5] = s;
    __syncthreads();
    if (threadIdx.x == 0) {
        float t = ws[0] + ws[1] + ws[2] + ws[3];
        if (isC) g_c2[row] = t;
        else     g_t2[row - NR] = t;
    }
}

// ---------------------------------------------------------------------------
// 2) tf32 mma.sync GEMM (C @ T^T), 128x128x32 tile, 256 thr, 3-stage cp.async,
//    ldmatrix fragment loads, fused logit epilogue.
// ---------------------------------------------------------------------------
#define NSTAGE 3
#define STAGE_BYTES 32768                       // A 16KB + B 16KB
#define SMEM_DYN (NSTAGE * STAGE_BYTES)         // 96 KB
#define NCHUNK 16                               // 512 / 32

__global__ __launch_bounds__(256, 2)
void k_gemm_tc(const float* __restrict__ Adummy, const float* __restrict__ Bdummy) {
    extern __shared__ char dsm[];
    const uint32_t smb = smem_u32(dsm);
    const int tid  = threadIdx.x;
    const int wid  = tid >> 5;
    const int lane = tid & 31;
    const int warp_m = wid >> 2;                // 0..1
    const int warp_n = wid & 3;                 // 0..3
    const int brow = blockIdx.y * 128;
    const int bcol = blockIdx.x * 128;

    const float* A = g_ca;
    const float* B = g_tb;

    float acc[4][4][4];
    #pragma unroll
    for (int i = 0; i < 4; i++)
        #pragma unroll
        for (int j = 0; j < 4; j++)
            #pragma unroll
            for (int d = 0; d < 4; d++) acc[i][j][d] = 0.0f;

    // cp.async stage loader: 128 rows x 32 floats per matrix
    const int lr = tid >> 3;                    // 0..31 (used twice -> 128 rows via i)
    const int lq = tid & 7;                     // 16B chunk within row
    auto issue_chunk = [&](int c) {
        const int s = c % NSTAGE;
        const uint32_t sA = smb + s * STAGE_BYTES;
        const uint32_t sB = sA + 16384;
        const float* gA = A + (size_t)brow * DD + c * 32;
        const float* gB = B + (size_t)bcol * DD + c * 32;
        #pragma unroll
        for (int i = 0; i < 4; i++) {
            int r = i * 32 + lr;
            uint32_t off = (uint32_t)(r * 128) + (uint32_t)(((lq ^ (r & 7)) << 4));
            const float* pA = gA + (size_t)r * DD + lq * 4;
            const float* pB = gB + (size_t)r * DD + lq * 4;
            asm volatile("cp.async.cg.shared.global [%0], [%1], 16;"
                         :: "r"(sA + off), "l"(pA) : "memory");
            asm volatile("cp.async.cg.shared.global [%0], [%1], 16;"
                         :: "r"(sB + off), "l"(pB) : "memory");
        }
        asm volatile("cp.async.commit_group;" ::: "memory");
    };

    issue_chunk(0); issue_chunk(1); issue_chunk(2);

    // per-thread ldmatrix address components
    const int t8 = lane >> 3;                   // tile index 0..3
    const int r8 = lane & 7;                    // row within tile
    uint32_t aoff[4], boff[2];
    #pragma unroll
    for (int mf = 0; mf < 4; mf++)
        aoff[mf] = (uint32_t)((warp_m * 64 + mf * 16 + (t8 & 1) * 8 + r8) * 128);
    #pragma unroll
    for (int nf2 = 0; nf2 < 2; nf2++)
        boff[nf2] = (uint32_t)((warp_n * 32 + nf2 * 16 + (t8 >> 1) * 8 + r8) * 128) + 16384u;
    const int xa = (t8 >> 1);                   // A seg low bit source
    const int xb = (t8 & 1);                    // B seg low bit source

    for (int c = 0; c < NCHUNK; c++) {
        asm volatile("cp.async.wait_group %0;" :: "n"(NSTAGE - 1) : "memory");
        __syncthreads();
        const uint32_t base = smb + (c % NSTAGE) * STAGE_BYTES;

        #pragma unroll
        for (int ks = 0; ks < 4; ks++) {
            uint32_t a[4][4], b[4][2];
            const uint32_t sgA = (uint32_t)(((ks * 2 + xa) ^ r8) << 4);
            const uint32_t sgB = (uint32_t)(((ks * 2 + xb) ^ r8) << 4);
            #pragma unroll
            for (int mf = 0; mf < 4; mf++)
                LDSM_X4(a[mf][0], a[mf][1], a[mf][2], a[mf][3],
                        base + aoff[mf] + sgA);
            #pragma unroll
            for (int nf2 = 0; nf2 < 2; nf2++)
                LDSM_X4(b[nf2 * 2][0], b[nf2 * 2][1],
                        b[nf2 * 2 + 1][0], b[nf2 * 2 + 1][1],
                        base + boff[nf2] + sgB);
            #pragma unroll
            for (int mf = 0; mf < 4; mf++)
                #pragma unroll
                for (int nf = 0; nf < 4; nf++)
                    MMA_TF32(acc[mf][nf],
                             a[mf][0], a[mf][1], a[mf][2], a[mf][3],
                             b[nf][0], b[nf][1]);
        }
        __syncthreads();
        if (c + NSTAGE < NCHUNK) issue_chunk(c + NSTAGE);
    }

    // ----- epilogue: logits + off-diag sum(1/(1+d2)) -----
    const int g = lane >> 2;                    // row within frag half
    const int q = lane & 3;                     // col pair
    float c2v[8], t2v[8];
    #pragma unroll
    for (int mf = 0; mf < 4; mf++) {
        c2v[mf * 2]     = g_c2[brow + warp_m * 64 + mf * 16 + g];
        c2v[mf * 2 + 1] = g_c2[brow + warp_m * 64 + mf * 16 + 8 + g];
    }
    #pragma unroll
    for (int nf = 0; nf < 4; nf++) {
        t2v[nf * 2]     = g_t2[bcol + warp_n * 32 + nf * 8 + q * 2];
        t2v[nf * 2 + 1] = g_t2[bcol + warp_n * 32 + nf * 8 + q * 2 + 1];
    }

    float sexp = 0.0f;
    #pragma unroll
    for (int mf = 0; mf < 4; mf++) {
        #pragma unroll
        for (int h = 0; h < 2; h++) {
            const int row = brow + warp_m * 64 + mf * 16 + h * 8 + g;
            #pragma unroll
            for (int nf = 0; nf < 4; nf++) {
                const int col = bcol + warp_n * 32 + nf * 8 + q * 2;
                float dot0 = acc[mf][nf][h * 2];
                float dot1 = acc[mf][nf][h * 2 + 1];
                float d20 = fmaxf(c2v[mf * 2 + h] + t2v[nf * 2]     - 2.0f * dot0, 0.0f);
                float d21 = fmaxf(c2v[mf * 2 + h] + t2v[nf * 2 + 1] - 2.0f * dot1, 0.0f);
                float lg0 = -log1pf(d20);
                float lg1 = -log1pf(d21);
                if (row != col)     sexp += __fdividef(1.0f, 1.0f + d20);
                if (row != col + 1) sexp += __fdividef(1.0f, 1.0f + d21);
                *(float2*)&g_logits[(size_t)row * NR + col] = make_float2(lg0, lg1);
            }
        }
    }

    // reduce sexp: warp -> CTA (smem reuse) -> bucketed atomic
    double se = (double)sexp;
    #pragma unroll
    for (int o = 16; o > 0; o >>= 1) se += __shfl_down_sync(0xffffffffu, se, o);
    double* red = (double*)dsm;
    __syncthreads();
    if (lane == 0) red[wid] = se;
    __syncthreads();
    if (tid == 0) {
        double t = 0.0;
        #pragma unroll
        for (int w = 0; w < 8; w++) t += red[w];
        atomicAdd(&g_sexp_bucket[(blockIdx.y * 64 + blockIdx.x) & 63], t);
    }
}

// ---------------------------------------------------------------------------
// 3a) log_baseline
// ---------------------------------------------------------------------------
__global__ void k_lb() {
    if (threadIdx.x == 0) {
        double s = 0.0;
        for (int i = 0; i < 64; i++) s += g_sexp_bucket[i];
        g_acc[0] = s;
        g_acc[7] = log(s) - log((double)NR * (double)(NR - 1));
    }
}

// ---------------------------------------------------------------------------
// 3b) diagonal statistics
// ---------------------------------------------------------------------------
__global__ void k_diag() {
    const float lbf = (float)g_acc[7];
    int tid = blockIdx.x * blockDim.x + threadIdx.x;
    int stride = gridDim.x * blockDim.x;
    float slog = 0.0f, ssig = 0.0f;
    int cnt = 0;
    for (int i = tid; i < NR; i += stride) {
        float x = g_logits[(size_t)i * (NR + 1)];
        float y = x - lbf;
        slog += x;
        ssig += 1.0f / (1.0f + expf(-y));
        cnt  += (y > 0.0f) ? 1 : 0;
    }
    double a = (double)slog, b = (double)ssig;
    int c = cnt;
    #pragma unroll
    for (int o = 16; o > 0; o >>= 1) {
        a += __shfl_down_sync(0xffffffffu, a, o);
        b += __shfl_down_sync(0xffffffffu, b, o);
        c += __shfl_down_sync(0xffffffffu, c, o);
    }
    if ((threadIdx.x & 31) == 0) {
        atomicAdd(&g_acc[1], a);
        atomicAdd(&g_acc[2], b);
        atomicAdd(&g_acc[3], (double)c);
    }
}

// ---------------------------------------------------------------------------
// 4) streaming stats over ALL logits
// ---------------------------------------------------------------------------
__global__ __launch_bounds__(256)
void k_stream() {
    const float lbf = (float)g_acc[7];
    const int tid = threadIdx.x;

    float  slog = 0.0f, ssig = 0.0f;
    int    cnt = 0;
    const size_t total4 = ((size_t)NR * NR) / 4;
    const size_t stride = (size_t)gridDim.x * blockDim.x;
    const float4* L4 = (const float4*)g_logits;

    for (size_t i = (size_t)blockIdx.x * blockDim.x + tid; i < total4; i += stride) {
        float4 v = L4[i];
        float y0 = v.x - lbf, y1 = v.y - lbf, y2 = v.z - lbf, y3 = v.w - lbf;
        slog += (v.x + v.y) + (v.z + v.w);
        ssig += 1.0f / (1.0f + expf(-y0));
        ssig += 1.0f / (1.0f + expf(-y1));
        ssig += 1.0f / (1.0f + expf(-y2));
        ssig += 1.0f / (1.0f + expf(-y3));
        cnt += (y0 > 0.0f) + (y1 > 0.0f) + (y2 > 0.0f) + (y3 > 0.0f);
    }

    __shared__ double r0[256], r1[256];
    __shared__ int    r2[256];
    r0[tid] = (double)slog; r1[tid] = (double)ssig; r2[tid] = cnt;
    __syncthreads();
    for (int s = 128; s > 0; s >>= 1) {
        if (tid < s) { r0[tid] += r0[tid + s]; r1[tid] += r1[tid + s]; r2[tid] += r2[tid + s]; }
        __syncthreads();
    }
    if (tid == 0) {
        atomicAdd(&g_acc[4], r0[0]);
        atomicAdd(&g_acc[5], r1[0]);
        atomicAdd(&g_acc[6], (double)r2[0]);
    }
}

// ---------------------------------------------------------------------------
// 5) finalize
// ---------------------------------------------------------------------------
__global__ void k_final(float* __restrict__ out) {
    if (threadIdx.x != 0 || blockIdx.x != 0) return;
    const double Npos = (double)NR;
    const double Nneg = (double)NR * (double)(NR - 1);

    double LB   = g_acc[7];
    double sdl  = g_acc[1];
    double sds  = g_acc[2];
    double cntd = g_acc[3];
    double sal  = g_acc[4];
    double sas  = g_acc[5];
    double cnta = g_acc[6];

    double pos_mean  = sdl / Npos - LB;
    double neg_mean  = (sal - sdl) / Nneg - LB;
    double repulsion = exp(-LB) * g_acc[0] / Nneg;
    double loss      = -pos_mean + repulsion;
    double sig_pos   = sds / Npos;
    double sig_neg   = (sas - sds) / Nneg;

    double TP = cntd / Npos;
    double FP = (cnta - cntd) / Nneg;
    double TN = 1.0 - FP;
    double FN = 1.0 - TP;
    double accuracy  = (TP + TN) * 0.5;
    double precision = TP / (TP + FP);
    double npv       = TN / (TN + FN);
    double apv       = (precision + npv) * 0.5;

    out[0]  = (float)loss;
    out[1]  = (float)pos_mean;
    out[2]  = (float)neg_mean;
    out[3]  = (float)sig_pos;
    out[4]  = (float)sig_neg;
    out[5]  = (float)LB;
    out[6]  = (float)accuracy;
    out[7]  = (float)precision;
    out[8]  = (float)npv;
    out[9]  = (float)apv;
    out[10] = (float)TP;
    out[11] = (float)TN;
}

// ---------------------------------------------------------------------------
// launch
// ---------------------------------------------------------------------------
extern "C" void kernel_launch(void* const* d_in, const int* in_sizes, int n_in,
                              void* d_out, int out_size) {
    const float* C = (const float*)d_in[0];
    const float* T = (const float*)d_in[1];
    float* out = (float*)d_out;

    static int configured = 0;
    if (!configured) {
        cudaFuncSetAttribute(k_gemm_tc, cudaFuncAttributeMaxDynamicSharedMemorySize, SMEM_DYN);
        configured = 1;
    }

    k_init<<<1, 64>>>();
    k_prep<<<2 * NR, 128>>>(C, T);
    dim3 grid(NR / 128, NR / 128);
    k_gemm_tc<<<grid, 256, SMEM_DYN>>>(C, T);
    k_lb<<<1, 1>>>();
    k_diag<<<32, 256>>>();
    k_stream<<<2048, 256>>>();
    k_final<<<1, 32>>>(out);
}

// round 5
// speedup vs baseline: 3.9636x; 1.1882x over previous
#include <cuda_runtime.h>
#include <cuda_fp16.h>
#include <cstdint>
#include <cstddef>

#define NR 8192
#define DD 512
#define LSHIFT 6.931472f   // ~ln(1024): centers logits near 0 for fp16 storage

// ---------------------------------------------------------------------------
// Device scratch (static — no cudaMalloc allowed)
// ---------------------------------------------------------------------------
__device__ __half g_l[(size_t)NR * NR];        // 134 MB: logit + LSHIFT, fp16
__device__ float  g_dd2[NR];                   // exact fp32 diagonal d2
__device__ float  g_ca[(size_t)NR * DD];       // tf32-rounded context
__device__ float  g_tb[(size_t)NR * DD];       // tf32-rounded target
__device__ float  g_c2[NR];
__device__ float  g_t2[NR];
// [0]=S_exp_off [1]=sum_logit_diag [2]=sum_sig_diag [3]=cnt_diag
// [4]=sum_logit_all [5]=sum_sig_all [6]=cnt_all [7]=log_baseline
__device__ double g_acc[16];
__device__ double g_sexp_bucket[64];
__device__ double g_slog_bucket[64];

// ---------------------------------------------------------------------------
// helpers
// ---------------------------------------------------------------------------
__device__ __forceinline__ uint32_t smem_u32(const void* p) {
    uint32_t a;
    asm("{ .reg .u64 t; cvta.to.shared.u64 t, %1; cvt.u32.u64 %0, t; }"
        : "=r"(a) : "l"(p));
    return a;
}

#define LDSM_X4(r0, r1, r2, r3, addr)                                   \
    asm volatile("ldmatrix.sync.aligned.m8n8.x4.shared.b16 "            \
                 "{%0,%1,%2,%3}, [%4];"                                 \
                 : "=r"(r0), "=r"(r1), "=r"(r2), "=r"(r3) : "r"(addr))

#define MMA_TF32(d, a0, a1, a2, a3, b0, b1)                             \
    asm volatile("mma.sync.aligned.m16n8k8.row.col.f32.tf32.tf32.f32 "  \
                 "{%0,%1,%2,%3}, {%4,%5,%6,%7}, {%8,%9}, {%0,%1,%2,%3};"\
                 : "+f"((d)[0]), "+f"((d)[1]), "+f"((d)[2]), "+f"((d)[3])\
                 : "r"(a0), "r"(a1), "r"(a2), "r"(a3), "r"(b0), "r"(b1))

__device__ __forceinline__ uint32_t to_tf32(float x) {
    uint32_t u;
    asm("cvt.rna.tf32.f32 %0, %1;" : "=r"(u) : "f"(x));
    return u;
}

// ---------------------------------------------------------------------------
// 0) zero accumulators
// ---------------------------------------------------------------------------
__global__ void k_init() {
    if (threadIdx.x < 16) g_acc[threadIdx.x] = 0.0;
    if (threadIdx.x < 64) { g_sexp_bucket[threadIdx.x] = 0.0; g_slog_bucket[threadIdx.x] = 0.0; }
}

// ---------------------------------------------------------------------------
// 1a/1b) prep: squared row norms (exact fp32) + tf32-rounded copies
// (two launches so k_gemm_tc is the 4th launch -> gets profiled by ncu)
// ---------------------------------------------------------------------------
__device__ __forceinline__ void prep_row(const float* __restrict__ src,
                                         float* __restrict__ dst,
                                         float* __restrict__ nrm, int row) {
    float4 v = ((const float4*)(src + (size_t)row * DD))[threadIdx.x];
    float s = v.x * v.x + v.y * v.y + v.z * v.z + v.w * v.w;

    uint4 r;
    r.x = to_tf32(v.x); r.y = to_tf32(v.y);
    r.z = to_tf32(v.z); r.w = to_tf32(v.w);
    ((uint4*)(dst + (size_t)row * DD))[threadIdx.x] = r;

    #pragma unroll
    for (int o = 16; o > 0; o >>= 1) s += __shfl_down_sync(0xffffffffu, s, o);
    __shared__ float ws[4];
    if ((threadIdx.x & 31) == 0) ws[threadIdx.x >> 5] = s;
    __syncthreads();
    if (threadIdx.x == 0) nrm[row] = ws[0] + ws[1] + ws[2] + ws[3];
}

__global__ void k_prepC(const float* __restrict__ C) {
    prep_row(C, g_ca, g_c2, blockIdx.x);
}
__global__ void k_prepT(const float* __restrict__ T) {
    prep_row(T, g_tb, g_t2, blockIdx.x);
}

// ---------------------------------------------------------------------------
// 2) tf32 mma.sync GEMM (C @ T^T), 128x128x32 tile, 256 thr, 3-stage cp.async,
//    ldmatrix fragment loads, fused epilogue:
//      store fp16 (logit+LSHIFT), slog = sum logit, sexp = sum p offdiag,
//      exact diag d2 -> g_dd2.
// ---------------------------------------------------------------------------
#define NSTAGE 3
#define STAGE_BYTES 32768                       // A 16KB + B 16KB
#define SMEM_DYN (NSTAGE * STAGE_BYTES)         // 96 KB
#define NCHUNK 16                               // 512 / 32

__global__ __launch_bounds__(256, 2)
void k_gemm_tc() {
    extern __shared__ char dsm[];
    const uint32_t smb = smem_u32(dsm);
    const int tid  = threadIdx.x;
    const int wid  = tid >> 5;
    const int lane = tid & 31;
    const int warp_m = wid >> 2;                // 0..1
    const int warp_n = wid & 3;                 // 0..3
    const int brow = blockIdx.y * 128;
    const int bcol = blockIdx.x * 128;

    const float* A = g_ca;
    const float* B = g_tb;

    float acc[4][4][4];
    #pragma unroll
    for (int i = 0; i < 4; i++)
        #pragma unroll
        for (int j = 0; j < 4; j++)
            #pragma unroll
            for (int d = 0; d < 4; d++) acc[i][j][d] = 0.0f;

    const int lr = tid >> 3;                    // 0..31
    const int lq = tid & 7;                     // 16B chunk within row
    auto issue_chunk = [&](int c) {
        const int s = c % NSTAGE;
        const uint32_t sA = smb + s * STAGE_BYTES;
        const uint32_t sB = sA + 16384;
        const float* gA = A + (size_t)brow * DD + c * 32;
        const float* gB = B + (size_t)bcol * DD + c * 32;
        #pragma unroll
        for (int i = 0; i < 4; i++) {
            int r = i * 32 + lr;
            uint32_t off = (uint32_t)(r * 128) + (uint32_t)(((lq ^ (r & 7)) << 4));
            const float* pA = gA + (size_t)r * DD + lq * 4;
            const float* pB = gB + (size_t)r * DD + lq * 4;
            asm volatile("cp.async.cg.shared.global [%0], [%1], 16;"
                         :: "r"(sA + off), "l"(pA) : "memory");
            asm volatile("cp.async.cg.shared.global [%0], [%1], 16;"
                         :: "r"(sB + off), "l"(pB) : "memory");
        }
        asm volatile("cp.async.commit_group;" ::: "memory");
    };

    issue_chunk(0); issue_chunk(1); issue_chunk(2);

    const int t8 = lane >> 3;
    const int r8 = lane & 7;
    uint32_t aoff[4], boff[2];
    #pragma unroll
    for (int mf = 0; mf < 4; mf++)
        aoff[mf] = (uint32_t)((warp_m * 64 + mf * 16 + (t8 & 1) * 8 + r8) * 128);
    #pragma unroll
    for (int nf2 = 0; nf2 < 2; nf2++)
        boff[nf2] = (uint32_t)((warp_n * 32 + nf2 * 16 + (t8 >> 1) * 8 + r8) * 128) + 16384u;
    const int xa = (t8 >> 1);
    const int xb = (t8 & 1);

    for (int c = 0; c < NCHUNK; c++) {
        asm volatile("cp.async.wait_group %0;" :: "n"(NSTAGE - 1) : "memory");
        __syncthreads();
        const uint32_t base = smb + (c % NSTAGE) * STAGE_BYTES;

        #pragma unroll
        for (int ks = 0; ks < 4; ks++) {
            uint32_t a[4][4], b[4][2];
            const uint32_t sgA = (uint32_t)(((ks * 2 + xa) ^ r8) << 4);
            const uint32_t sgB = (uint32_t)(((ks * 2 + xb) ^ r8) << 4);
            #pragma unroll
            for (int mf = 0; mf < 4; mf++)
                LDSM_X4(a[mf][0], a[mf][1], a[mf][2], a[mf][3],
                        base + aoff[mf] + sgA);
            #pragma unroll
            for (int nf2 = 0; nf2 < 2; nf2++)
                LDSM_X4(b[nf2 * 2][0], b[nf2 * 2][1],
                        b[nf2 * 2 + 1][0], b[nf2 * 2 + 1][1],
                        base + boff[nf2] + sgB);
            #pragma unroll
            for (int mf = 0; mf < 4; mf++)
                #pragma unroll
                for (int nf = 0; nf < 4; nf++)
                    MMA_TF32(acc[mf][nf],
                             a[mf][0], a[mf][1], a[mf][2], a[mf][3],
                             b[nf][0], b[nf][1]);
        }
        __syncthreads();
        if (c + NSTAGE < NCHUNK) issue_chunk(c + NSTAGE);
    }

    // ----- epilogue -----
    const int g = lane >> 2;                    // row within frag half
    const int q = lane & 3;                     // col pair
    float c2v[8], t2v[8];
    #pragma unroll
    for (int mf = 0; mf < 4; mf++) {
        c2v[mf * 2]     = g_c2[brow + warp_m * 64 + mf * 16 + g];
        c2v[mf * 2 + 1] = g_c2[brow + warp_m * 64 + mf * 16 + 8 + g];
    }
    #pragma unroll
    for (int nf = 0; nf < 4; nf++) {
        t2v[nf * 2]     = g_t2[bcol + warp_n * 32 + nf * 8 + q * 2];
        t2v[nf * 2 + 1] = g_t2[bcol + warp_n * 32 + nf * 8 + q * 2 + 1];
    }

    float sexp = 0.0f;     // off-diagonal sum of p = 1/(1+d2)
    float slog = 0.0f;     // all-inclusive sum of logit = -log(1+d2)
    #pragma unroll
    for (int mf = 0; mf < 4; mf++) {
        #pragma unroll
        for (int h = 0; h < 2; h++) {
            const int row = brow + warp_m * 64 + mf * 16 + h * 8 + g;
            #pragma unroll
            for (int nf = 0; nf < 4; nf++) {
                const int col = bcol + warp_n * 32 + nf * 8 + q * 2;
                float dot0 = acc[mf][nf][h * 2];
                float dot1 = acc[mf][nf][h * 2 + 1];
                float u0 = fmaxf(c2v[mf * 2 + h] + t2v[nf * 2]     - 2.0f * dot0, 0.0f) + 1.0f;
                float u1 = fmaxf(c2v[mf * 2 + h] + t2v[nf * 2 + 1] - 2.0f * dot1, 0.0f) + 1.0f;
                float lg0 = -__logf(u0);
                float lg1 = -__logf(u1);
                slog += lg0 + lg1;
                if (row != col)     sexp += __fdividef(1.0f, u0);
                if (row != col + 1) sexp += __fdividef(1.0f, u1);
                if (row == col)     g_dd2[row] = u0 - 1.0f;
                if (row == col + 1) g_dd2[row] = u1 - 1.0f;
                *(__half2*)&g_l[(size_t)row * NR + col] =
                    __floats2half2_rn(lg0 + LSHIFT, lg1 + LSHIFT);
            }
        }
    }

    // reduce (sexp, slog): warp -> CTA -> bucketed atomic
    double se = (double)sexp;
    double sl = (double)slog;
    #pragma unroll
    for (int o = 16; o > 0; o >>= 1) {
        se += __shfl_down_sync(0xffffffffu, se, o);
        sl += __shfl_down_sync(0xffffffffu, sl, o);
    }
    double* red = (double*)dsm;
    __syncthreads();
    if (lane == 0) { red[wid] = se; red[8 + wid] = sl; }
    __syncthreads();
    if (tid == 0) {
        double t0 = 0.0, t1 = 0.0;
        #pragma unroll
        for (int w = 0; w < 8; w++) { t0 += red[w]; t1 += red[8 + w]; }
        int bk = (blockIdx.y * 64 + blockIdx.x) & 63;
        atomicAdd(&g_sexp_bucket[bk], t0);
        atomicAdd(&g_slog_bucket[bk], t1);
    }
}

// ---------------------------------------------------------------------------
// 3a) reduce buckets, compute log_baseline
// ---------------------------------------------------------------------------
__global__ void k_lb() {
    if (threadIdx.x == 0) {
        double s = 0.0, l = 0.0;
        for (int i = 0; i < 64; i++) { s += g_sexp_bucket[i]; l += g_slog_bucket[i]; }
        g_acc[0] = s;
        g_acc[4] = l;
        g_acc[7] = log(s) - log((double)NR * (double)(NR - 1));
    }
}

// ---------------------------------------------------------------------------
// 3b) diagonal statistics from exact fp32 d2
// ---------------------------------------------------------------------------
__global__ void k_diag() {
    const float lbf = (float)g_acc[7];
    int tid = blockIdx.x * blockDim.x + threadIdx.x;
    int stride = gridDim.x * blockDim.x;
    float slog = 0.0f, ssig = 0.0f;
    int cnt = 0;
    for (int i = tid; i < NR; i += stride) {
        float d2 = g_dd2[i];
        float x = -log1pf(d2);
        float y = x - lbf;
        slog += x;
        ssig += 1.0f / (1.0f + expf(-y));
        cnt  += (y > 0.0f) ? 1 : 0;
    }
    double a = (double)slog, b = (double)ssig;
    int c = cnt;
    #pragma unroll
    for (int o = 16; o > 0; o >>= 1) {
        a += __shfl_down_sync(0xffffffffu, a, o);
        b += __shfl_down_sync(0xffffffffu, b, o);
        c += __shfl_down_sync(0xffffffffu, c, o);
    }
    if ((threadIdx.x & 31) == 0) {
        atomicAdd(&g_acc[1], a);
        atomicAdd(&g_acc[2], b);
        atomicAdd(&g_acc[3], (double)c);
    }
}

// ---------------------------------------------------------------------------
// 4) streaming stats over all shifted logits (fp16):
//    thr = LB + LSHIFT; cnt(l > thr), sum sigmoid(l - thr)
// ---------------------------------------------------------------------------
__global__ __launch_bounds__(256)
void k_stream() {
    const float thr = (float)g_acc[7] + LSHIFT;
    const int tid = threadIdx.x;

    float  ssig = 0.0f;
    int    cnt = 0;
    const size_t total8 = ((size_t)NR * NR) / 8;          // uint4 = 8 halves
    const size_t stride = (size_t)gridDim.x * blockDim.x;
    const uint4* P8 = (const uint4*)g_l;

    for (size_t i = (size_t)blockIdx.x * blockDim.x + tid; i < total8; i += stride) {
        uint4 v = P8[i];
        float2 f0 = __half22float2(*(__half2*)&v.x);
        float2 f1 = __half22float2(*(__half2*)&v.y);
        float2 f2 = __half22float2(*(__half2*)&v.z);
        float2 f3 = __half22float2(*(__half2*)&v.w);
        float y0 = f0.x - thr, y1 = f0.y - thr, y2 = f1.x - thr, y3 = f1.y - thr;
        float y4 = f2.x - thr, y5 = f2.y - thr, y6 = f3.x - thr, y7 = f3.y - thr;
        ssig += __fdividef(1.0f, 1.0f + __expf(-y0)) + __fdividef(1.0f, 1.0f + __expf(-y1));
        ssig += __fdividef(1.0f, 1.0f + __expf(-y2)) + __fdividef(1.0f, 1.0f + __expf(-y3));
        ssig += __fdividef(1.0f, 1.0f + __expf(-y4)) + __fdividef(1.0f, 1.0f + __expf(-y5));
        ssig += __fdividef(1.0f, 1.0f + __expf(-y6)) + __fdividef(1.0f, 1.0f + __expf(-y7));
        cnt += (y0 > 0.0f) + (y1 > 0.0f) + (y2 > 0.0f) + (y3 > 0.0f)
             + (y4 > 0.0f) + (y5 > 0.0f) + (y6 > 0.0f) + (y7 > 0.0f);
    }

    __shared__ double r1[256];
    __shared__ int    r2[256];
    r1[tid] = (double)ssig; r2[tid] = cnt;
    __syncthreads();
    for (int s = 128; s > 0; s >>= 1) {
        if (tid < s) { r1[tid] += r1[tid + s]; r2[tid] += r2[tid + s]; }
        __syncthreads();
    }
    if (tid == 0) {
        atomicAdd(&g_acc[5], r1[0]);
        atomicAdd(&g_acc[6], (double)r2[0]);
    }
}

// ---------------------------------------------------------------------------
// 5) finalize
// ---------------------------------------------------------------------------
__global__ void k_final(float* __restrict__ out) {
    if (threadIdx.x != 0 || blockIdx.x != 0) return;
    const double Npos = (double)NR;
    const double Nneg = (double)NR * (double)(NR - 1);

    double LB   = g_acc[7];
    double sdl  = g_acc[1];
    double sds  = g_acc[2];
    double cntd = g_acc[3];
    double sal  = g_acc[4];
    double sas  = g_acc[5];
    double cnta = g_acc[6];

    double pos_mean  = sdl / Npos - LB;
    double neg_mean  = (sal - sdl) / Nneg - LB;
    double repulsion = exp(-LB) * g_acc[0] / Nneg;
    double loss      = -pos_mean + repulsion;
    double sig_pos   = sds / Npos;
    double sig_neg   = (sas - sds) / Nneg;

    double TP = cntd / Npos;
    double FP = (cnta - cntd) / Nneg;
    double TN = 1.0 - FP;
    double FN = 1.0 - TP;
    double accuracy  = (TP + TN) * 0.5;
    double precision = TP / (TP + FP);
    double npv       = TN / (TN + FN);
    double apv       = (precision + npv) * 0.5;

    out[0]  = (float)loss;
    out[1]  = (float)pos_mean;
    out[2]  = (float)neg_mean;
    out[3]  = (float)sig_pos;
    out[4]  = (float)sig_neg;
    out[5]  = (float)LB;
    out[6]  = (float)accuracy;
    out[7]  = (float)precision;
    out[8]  = (float)npv;
    out[9]  = (float)apv;
    out[10] = (float)TP;
    out[11] = (float)TN;
}

// ---------------------------------------------------------------------------
// launch
// ---------------------------------------------------------------------------
extern "C" void kernel_launch(void* const* d_in, const int* in_sizes, int n_in,
                              void* d_out, int out_size) {
    const float* C = (const float*)d_in[0];
    const float* T = (const float*)d_in[1];
    float* out = (float*)d_out;

    static int configured = 0;
    if (!configured) {
        cudaFuncSetAttribute(k_gemm_tc, cudaFuncAttributeMaxDynamicSharedMemorySize, SMEM_DYN);
        configured = 1;
    }

    k_init<<<1, 64>>>();                     // launch 0
    k_prepC<<<NR, 128>>>(C);                 // launch 1
    k_prepT<<<NR, 128>>>(T);                 // launch 2
    dim3 grid(NR / 128, NR / 128);
    k_gemm_tc<<<grid, 256, SMEM_DYN>>>();    // launch 3  <- ncu capture slot
    k_lb<<<1, 1>>>();                        // launch 4
    k_diag<<<32, 256>>>();                   // launch 5
    k_stream<<<2048, 256>>>();               // launch 6
    k_final<<<1, 32>>>(out);                 // launch 7
}

// round 6
// speedup vs baseline: 6.0000x; 1.5138x over previous
#include <cuda_runtime.h>
#include <cuda_fp16.h>
#include <cstdint>
#include <cstddef>

#define NR 8192
#define DD 512
#define LSHIFT 6.931472f   // ~ln(1024): centers logits near 0 for fp16 storage

// ---------------------------------------------------------------------------
// Device scratch (static — no cudaMalloc allowed)
// ---------------------------------------------------------------------------
__device__ __half g_l[(size_t)NR * NR];        // 134 MB: logit + LSHIFT, fp16
__device__ float  g_dd2[NR];                   // exact fp32 diagonal d2
__device__ __half g_ca[(size_t)NR * DD];       // fp16-rounded context
__device__ __half g_tb[(size_t)NR * DD];       // fp16-rounded target
__device__ float  g_c2[NR];                    // ||c_h||^2 of rounded values
__device__ float  g_t2[NR];
// [0]=S_exp_off [1]=sum_logit_diag [2]=sum_sig_diag [3]=cnt_diag
// [4]=sum_logit_all [5]=sum_sig_all [6]=cnt_all [7]=log_baseline
__device__ double g_acc[16];
__device__ double g_sexp_bucket[64];
__device__ double g_slog_bucket[64];

// ---------------------------------------------------------------------------
// helpers
// ---------------------------------------------------------------------------
__device__ __forceinline__ uint32_t smem_u32(const void* p) {
    uint32_t a;
    asm("{ .reg .u64 t; cvta.to.shared.u64 t, %1; cvt.u32.u64 %0, t; }"
        : "=r"(a) : "l"(p));
    return a;
}

#define LDSM_X4(r0, r1, r2, r3, addr)                                   \
    asm volatile("ldmatrix.sync.aligned.m8n8.x4.shared.b16 "            \
                 "{%0,%1,%2,%3}, [%4];"                                 \
                 : "=r"(r0), "=r"(r1), "=r"(r2), "=r"(r3) : "r"(addr))

#define MMA_F16(d, a0, a1, a2, a3, b0, b1)                              \
    asm volatile("mma.sync.aligned.m16n8k16.row.col.f32.f16.f16.f32 "   \
                 "{%0,%1,%2,%3}, {%4,%5,%6,%7}, {%8,%9}, {%0,%1,%2,%3};"\
                 : "+f"((d)[0]), "+f"((d)[1]), "+f"((d)[2]), "+f"((d)[3])\
                 : "r"(a0), "r"(a1), "r"(a2), "r"(a3), "r"(b0), "r"(b1))

// ---------------------------------------------------------------------------
// 0) zero accumulators
// ---------------------------------------------------------------------------
__global__ void k_init() {
    if (threadIdx.x < 16) g_acc[threadIdx.x] = 0.0;
    if (threadIdx.x < 64) { g_sexp_bucket[threadIdx.x] = 0.0; g_slog_bucket[threadIdx.x] = 0.0; }
}

// ---------------------------------------------------------------------------
// 1a/1b) prep: fp16-rounded copies + squared row norms OF THE ROUNDED values
// (two launches so k_gemm_tc is the 4th launch -> gets profiled by ncu)
// ---------------------------------------------------------------------------
__device__ __forceinline__ void prep_row(const float* __restrict__ src,
                                         __half* __restrict__ dst,
                                         float* __restrict__ nrm, int row) {
    float4 v = ((const float4*)(src + (size_t)row * DD))[threadIdx.x];
    __half2 h0 = __floats2half2_rn(v.x, v.y);
    __half2 h1 = __floats2half2_rn(v.z, v.w);
    ((uint2*)(dst + (size_t)row * DD))[threadIdx.x] =
        make_uint2(*(uint32_t*)&h0, *(uint32_t*)&h1);

    // norms from the ROUNDED values so d2 = c2+t2-2dot is consistent
    float2 f0 = __half22float2(h0);
    float2 f1 = __half22float2(h1);
    float s = f0.x * f0.x + f0.y * f0.y + f1.x * f1.x + f1.y * f1.y;

    #pragma unroll
    for (int o = 16; o > 0; o >>= 1) s += __shfl_down_sync(0xffffffffu, s, o);
    __shared__ float ws[4];
    if ((threadIdx.x & 31) == 0) ws[threadIdx.x >> 5] = s;
    __syncthreads();
    if (threadIdx.x == 0) nrm[row] = ws[0] + ws[1] + ws[2] + ws[3];
}

__global__ void k_prepC(const float* __restrict__ C) {
    prep_row(C, g_ca, g_c2, blockIdx.x);
}
__global__ void k_prepT(const float* __restrict__ T) {
    prep_row(T, g_tb, g_t2, blockIdx.x);
}

// ---------------------------------------------------------------------------
// 2) fp16 mma.sync GEMM (C @ T^T), 128x128x64 tile, 256 thr, 3-stage cp.async,
//    ldmatrix fragment loads, fused epilogue:
//      store fp16 (logit+LSHIFT), slog = sum logit, sexp = sum p offdiag,
//      exact diag d2 -> g_dd2.
//    Each stage: 128 rows x 64 halves (128B/row, SW128) per matrix = 16KB.
// ---------------------------------------------------------------------------
#define NSTAGE 3
#define STAGE_BYTES 32768                       // A 16KB + B 16KB
#define SMEM_DYN (NSTAGE * STAGE_BYTES)         // 96 KB
#define NCHUNK 8                                // 512 / 64

__global__ __launch_bounds__(256, 2)
void k_gemm_tc() {
    extern __shared__ char dsm[];
    const uint32_t smb = smem_u32(dsm);
    const int tid  = threadIdx.x;
    const int wid  = tid >> 5;
    const int lane = tid & 31;
    const int warp_m = wid >> 2;                // 0..1
    const int warp_n = wid & 3;                 // 0..3
    const int brow = blockIdx.y * 128;
    const int bcol = blockIdx.x * 128;

    const __half* A = g_ca;
    const __half* B = g_tb;

    float acc[4][4][4];
    #pragma unroll
    for (int i = 0; i < 4; i++)
        #pragma unroll
        for (int j = 0; j < 4; j++)
            #pragma unroll
            for (int d = 0; d < 4; d++) acc[i][j][d] = 0.0f;

    const int lr = tid >> 3;                    // 0..31
    const int lq = tid & 7;                     // 16B segment within 128B row
    auto issue_chunk = [&](int c) {
        const int s = c % NSTAGE;
        const uint32_t sA = smb + s * STAGE_BYTES;
        const uint32_t sB = sA + 16384;
        const __half* gA = A + (size_t)brow * DD + c * 64;
        const __half* gB = B + (size_t)bcol * DD + c * 64;
        #pragma unroll
        for (int i = 0; i < 4; i++) {
            int r = i * 32 + lr;
            uint32_t off = (uint32_t)(r * 128) + (uint32_t)(((lq ^ (r & 7)) << 4));
            const __half* pA = gA + (size_t)r * DD + lq * 8;
            const __half* pB = gB + (size_t)r * DD + lq * 8;
            asm volatile("cp.async.cg.shared.global [%0], [%1], 16;"
                         :: "r"(sA + off), "l"(pA) : "memory");
            asm volatile("cp.async.cg.shared.global [%0], [%1], 16;"
                         :: "r"(sB + off), "l"(pB) : "memory");
        }
        asm volatile("cp.async.commit_group;" ::: "memory");
    };

    issue_chunk(0); issue_chunk(1); issue_chunk(2);

    const int t8 = lane >> 3;
    const int r8 = lane & 7;
    uint32_t aoff[4], boff[2];
    #pragma unroll
    for (int mf = 0; mf < 4; mf++)
        aoff[mf] = (uint32_t)((warp_m * 64 + mf * 16 + (t8 & 1) * 8 + r8) * 128);
    #pragma unroll
    for (int nf2 = 0; nf2 < 2; nf2++)
        boff[nf2] = (uint32_t)((warp_n * 32 + nf2 * 16 + (t8 >> 1) * 8 + r8) * 128) + 16384u;
    const int xa = (t8 >> 1);                   // A: k-half selector
    const int xb = (t8 & 1);                    // B: k-half selector

    for (int c = 0; c < NCHUNK; c++) {
        asm volatile("cp.async.wait_group %0;" :: "n"(NSTAGE - 1) : "memory");
        __syncthreads();
        const uint32_t base = smb + (c % NSTAGE) * STAGE_BYTES;

        #pragma unroll
        for (int ks = 0; ks < 4; ks++) {        // 4 x k16 = 64
            uint32_t a[4][4], b[4][2];
            const uint32_t sgA = (uint32_t)(((ks * 2 + xa) ^ r8) << 4);
            const uint32_t sgB = (uint32_t)(((ks * 2 + xb) ^ r8) << 4);
            #pragma unroll
            for (int mf = 0; mf < 4; mf++)
                LDSM_X4(a[mf][0], a[mf][1], a[mf][2], a[mf][3],
                        base + aoff[mf] + sgA);
            #pragma unroll
            for (int nf2 = 0; nf2 < 2; nf2++)
                LDSM_X4(b[nf2 * 2][0], b[nf2 * 2][1],
                        b[nf2 * 2 + 1][0], b[nf2 * 2 + 1][1],
                        base + boff[nf2] + sgB);
            #pragma unroll
            for (int mf = 0; mf < 4; mf++)
                #pragma unroll
                for (int nf = 0; nf < 4; nf++)
                    MMA_F16(acc[mf][nf],
                            a[mf][0], a[mf][1], a[mf][2], a[mf][3],
                            b[nf][0], b[nf][1]);
        }
        __syncthreads();
        if (c + NSTAGE < NCHUNK) issue_chunk(c + NSTAGE);
    }

    // ----- epilogue -----
    const int g = lane >> 2;                    // row within frag half
    const int q = lane & 3;                     // col pair
    float c2v[8], t2v[8];
    #pragma unroll
    for (int mf = 0; mf < 4; mf++) {
        c2v[mf * 2]     = g_c2[brow + warp_m * 64 + mf * 16 + g];
        c2v[mf * 2 + 1] = g_c2[brow + warp_m * 64 + mf * 16 + 8 + g];
    }
    #pragma unroll
    for (int nf = 0; nf < 4; nf++) {
        t2v[nf * 2]     = g_t2[bcol + warp_n * 32 + nf * 8 + q * 2];
        t2v[nf * 2 + 1] = g_t2[bcol + warp_n * 32 + nf * 8 + q * 2 + 1];
    }

    float sexp = 0.0f;     // off-diagonal sum of p = 1/(1+d2)
    float slog = 0.0f;     // all-inclusive sum of logit = -log(1+d2)
    #pragma unroll
    for (int mf = 0; mf < 4; mf++) {
        #pragma unroll
        for (int h = 0; h < 2; h++) {
            const int row = brow + warp_m * 64 + mf * 16 + h * 8 + g;
            #pragma unroll
            for (int nf = 0; nf < 4; nf++) {
                const int col = bcol + warp_n * 32 + nf * 8 + q * 2;
                float dot0 = acc[mf][nf][h * 2];
                float dot1 = acc[mf][nf][h * 2 + 1];
                float u0 = fmaxf(c2v[mf * 2 + h] + t2v[nf * 2]     - 2.0f * dot0, 0.0f) + 1.0f;
                float u1 = fmaxf(c2v[mf * 2 + h] + t2v[nf * 2 + 1] - 2.0f * dot1, 0.0f) + 1.0f;
                float lg0 = -__logf(u0);
                float lg1 = -__logf(u1);
                slog += lg0 + lg1;
                if (row != col)     sexp += __fdividef(1.0f, u0);
                if (row != col + 1) sexp += __fdividef(1.0f, u1);
                if (row == col)     g_dd2[row] = u0 - 1.0f;
                if (row == col + 1) g_dd2[row] = u1 - 1.0f;
                *(__half2*)&g_l[(size_t)row * NR + col] =
                    __floats2half2_rn(lg0 + LSHIFT, lg1 + LSHIFT);
            }
        }
    }

    // reduce (sexp, slog): warp -> CTA -> bucketed atomic
    double se = (double)sexp;
    double sl = (double)slog;
    #pragma unroll
    for (int o = 16; o > 0; o >>= 1) {
        se += __shfl_down_sync(0xffffffffu, se, o);
        sl += __shfl_down_sync(0xffffffffu, sl, o);
    }
    double* red = (double*)dsm;
    __syncthreads();
    if (lane == 0) { red[wid] = se; red[8 + wid] = sl; }
    __syncthreads();
    if (tid == 0) {
        double t0 = 0.0, t1 = 0.0;
        #pragma unroll
        for (int w = 0; w < 8; w++) { t0 += red[w]; t1 += red[8 + w]; }
        int bk = (blockIdx.y * 64 + blockIdx.x) & 63;
        atomicAdd(&g_sexp_bucket[bk], t0);
        atomicAdd(&g_slog_bucket[bk], t1);
    }
}

// ---------------------------------------------------------------------------
// 3a) reduce buckets, compute log_baseline
// ---------------------------------------------------------------------------
__global__ void k_lb() {
    if (threadIdx.x == 0) {
        double s = 0.0, l = 0.0;
        for (int i = 0; i < 64; i++) { s += g_sexp_bucket[i]; l += g_slog_bucket[i]; }
        g_acc[0] = s;
        g_acc[4] = l;
        g_acc[7] = log(s) - log((double)NR * (double)(NR - 1));
    }
}

// ---------------------------------------------------------------------------
// 3b) diagonal statistics from exact fp32 d2
// ---------------------------------------------------------------------------
__global__ void k_diag() {
    const float lbf = (float)g_acc[7];
    int tid = blockIdx.x * blockDim.x + threadIdx.x;
    int stride = gridDim.x * blockDim.x;
    float slog = 0.0f, ssig = 0.0f;
    int cnt = 0;
    for (int i = tid; i < NR; i += stride) {
        float d2 = g_dd2[i];
        float x = -log1pf(d2);
        float y = x - lbf;
        slog += x;
        ssig += 1.0f / (1.0f + expf(-y));
        cnt  += (y > 0.0f) ? 1 : 0;
    }
    double a = (double)slog, b = (double)ssig;
    int c = cnt;
    #pragma unroll
    for (int o = 16; o > 0; o >>= 1) {
        a += __shfl_down_sync(0xffffffffu, a, o);
        b += __shfl_down_sync(0xffffffffu, b, o);
        c += __shfl_down_sync(0xffffffffu, c, o);
    }
    if ((threadIdx.x & 31) == 0) {
        atomicAdd(&g_acc[1], a);
        atomicAdd(&g_acc[2], b);
        atomicAdd(&g_acc[3], (double)c);
    }
}

// ---------------------------------------------------------------------------
// 4) streaming stats over all shifted logits (fp16):
//    thr = LB + LSHIFT; cnt(l > thr), sum sigmoid(l - thr)
// ---------------------------------------------------------------------------
__global__ __launch_bounds__(256)
void k_stream() {
    const float thr = (float)g_acc[7] + LSHIFT;
    const int tid = threadIdx.x;

    float  ssig = 0.0f;
    int    cnt = 0;
    const size_t total8 = ((size_t)NR * NR) / 8;          // uint4 = 8 halves
    const size_t stride = (size_t)gridDim.x * blockDim.x;
    const uint4* P8 = (const uint4*)g_l;

    for (size_t i = (size_t)blockIdx.x * blockDim.x + tid; i < total8; i += stride) {
        uint4 v = P8[i];
        float2 f0 = __half22float2(*(__half2*)&v.x);
        float2 f1 = __half22float2(*(__half2*)&v.y);
        float2 f2 = __half22float2(*(__half2*)&v.z);
        float2 f3 = __half22float2(*(__half2*)&v.w);
        float y0 = f0.x - thr, y1 = f0.y - thr, y2 = f1.x - thr, y3 = f1.y - thr;
        float y4 = f2.x - thr, y5 = f2.y - thr, y6 = f3.x - thr, y7 = f3.y - thr;
        ssig += __fdividef(1.0f, 1.0f + __expf(-y0)) + __fdividef(1.0f, 1.0f + __expf(-y1));
        ssig += __fdividef(1.0f, 1.0f + __expf(-y2)) + __fdividef(1.0f, 1.0f + __expf(-y3));
        ssig += __fdividef(1.0f, 1.0f + __expf(-y4)) + __fdividef(1.0f, 1.0f + __expf(-y5));
        ssig += __fdividef(1.0f, 1.0f + __expf(-y6)) + __fdividef(1.0f, 1.0f + __expf(-y7));
        cnt += (y0 > 0.0f) + (y1 > 0.0f) + (y2 > 0.0f) + (y3 > 0.0f)
             + (y4 > 0.0f) + (y5 > 0.0f) + (y6 > 0.0f) + (y7 > 0.0f);
    }

    __shared__ double r1[256];
    __shared__ int    r2[256];
    r1[tid] = (double)ssig; r2[tid] = cnt;
    __syncthreads();
    for (int s = 128; s > 0; s >>= 1) {
        if (tid < s) { r1[tid] += r1[tid + s]; r2[tid] += r2[tid + s]; }
        __syncthreads();
    }
    if (tid == 0) {
        atomicAdd(&g_acc[5], r1[0]);
        atomicAdd(&g_acc[6], (double)r2[0]);
    }
}

// ---------------------------------------------------------------------------
// 5) finalize
// ---------------------------------------------------------------------------
__global__ void k_final(float* __restrict__ out) {
    if (threadIdx.x != 0 || blockIdx.x != 0) return;
    const double Npos = (double)NR;
    const double Nneg = (double)NR * (double)(NR - 1);

    double LB   = g_acc[7];
    double sdl  = g_acc[1];
    double sds  = g_acc[2];
    double cntd = g_acc[3];
    double sal  = g_acc[4];
    double sas  = g_acc[5];
    double cnta = g_acc[6];

    double pos_mean  = sdl / Npos - LB;
    double neg_mean  = (sal - sdl) / Nneg - LB;
    double repulsion = exp(-LB) * g_acc[0] / Nneg;
    double loss      = -pos_mean + repulsion;
    double sig_pos   = sds / Npos;
    double sig_neg   = (sas - sds) / Nneg;

    double TP = cntd / Npos;
    double FP = (cnta - cntd) / Nneg;
    double TN = 1.0 - FP;
    double FN = 1.0 - TP;
    double accuracy  = (TP + TN) * 0.5;
    double precision = TP / (TP + FP);
    double npv       = TN / (TN + FN);
    double apv       = (precision + npv) * 0.5;

    out[0]  = (float)loss;
    out[1]  = (float)pos_mean;
    out[2]  = (float)neg_mean;
    out[3]  = (float)sig_pos;
    out[4]  = (float)sig_neg;
    out[5]  = (float)LB;
    out[6]  = (float)accuracy;
    out[7]  = (float)precision;
    out[8]  = (float)npv;
    out[9]  = (float)apv;
    out[10] = (float)TP;
    out[11] = (float)TN;
}

// ---------------------------------------------------------------------------
// launch
// ---------------------------------------------------------------------------
extern "C" void kernel_launch(void* const* d_in, const int* in_sizes, int n_in,
                              void* d_out, int out_size) {
    const float* C = (const float*)d_in[0];
    const float* T = (const float*)d_in[1];
    float* out = (float*)d_out;

    static int configured = 0;
    if (!configured) {
        cudaFuncSetAttribute(k_gemm_tc, cudaFuncAttributeMaxDynamicSharedMemorySize, SMEM_DYN);
        configured = 1;
    }

    k_init<<<1, 64>>>();                     // launch 0
    k_prepC<<<NR, 128>>>(C);                 // launch 1
    k_prepT<<<NR, 128>>>(T);                 // launch 2
    dim3 grid(NR / 128, NR / 128);
    k_gemm_tc<<<grid, 256, SMEM_DYN>>>();    // launch 3  <- ncu capture slot
    k_lb<<<1, 1>>>();                        // launch 4
    k_diag<<<32, 256>>>();                   // launch 5
    k_stream<<<2048, 256>>>();               // launch 6
    k_final<<<1, 32>>>(out);                 // launch 7
}